// round 3
// baseline (speedup 1.0000x reference)
#include <cuda_runtime.h>
#include <math.h>

#define N_NODES 20000
#define D 128
#define E_EDGES 640000

// Scratch (static device globals; no allocation allowed)
__device__ unsigned g_agg[N_NODES * D];   // order-encoded running max
__device__ float    g_h[N_NODES * D];     // layer-1 output

// ---- order-preserving float<->uint encoding for atomicMax ----
__device__ __forceinline__ unsigned enc_f(float f) {
    unsigned b = __float_as_uint(f);
    return (b & 0x80000000u) ? ~b : (b | 0x80000000u);
}
__device__ __forceinline__ float dec_f(unsigned u) {
    if (u == 0u) return 0.0f;  // untouched -> empty segment -> 0 (PyG fill)
    unsigned b = (u & 0x80000000u) ? (u & 0x7FFFFFFFu) : ~u;
    return __uint_as_float(b);
}

__device__ __forceinline__ float gelu_exact(float v) {
    return 0.5f * v * (1.0f + erff(v * 0.70710678118654752f));
}

// ---------------- init agg to sentinel 0 ----------------
__global__ void k_init() {
    int i = blockIdx.x * blockDim.x + threadIdx.x;
    if (i < N_NODES * D / 4) {
        uint4 z = make_uint4(0u, 0u, 0u, 0u);
        reinterpret_cast<uint4*>(g_agg)[i] = z;
    }
}

// ---------------- copy edge_weight to output tail ----------------
__global__ void k_copy_ew(const float* __restrict__ ew, float* __restrict__ dst) {
    int i = blockIdx.x * blockDim.x + threadIdx.x;
    if (i < E_EDGES / 4) {
        reinterpret_cast<float4*>(dst)[i] = reinterpret_cast<const float4*>(ew)[i];
    }
}

// ---------------- scatter max: msg = ew[e] * x[src], atomicMax into dst ----------------
// edge_index is int32 (JAX default x64-disabled downcasts int64 -> int32).
__global__ void __launch_bounds__(256) k_scatter(const float* __restrict__ x,
                                                 const int* __restrict__ ei,
                                                 const float* __restrict__ ew) {
    int e = blockIdx.x * 2 + (threadIdx.x >> 7);
    int d = threadIdx.x & 127;
    if (e >= E_EDGES) return;
    int s = ei[e];
    int t = ei[E_EDGES + e];
    float w = __ldg(&ew[e]);
    float v = w * __ldg(&x[s * D + d]);
    atomicMax(&g_agg[t * D + d], enc_f(v));
}

// ---------------- fused GEMM + bias + GELU + skip + LayerNorm ----------------
// MODE 0 (layer 1): acc = agg@W1^T + A@W2^T   (A = x); skip = x; dst = g_h
// MODE 1 (layer 2): acc = g_h@W1^T;            skip = g_h; dst = out
// Block: 256 threads, tile 64 nodes x 128 cols, microtile 4n x 8d, kT = 16.
template<int MODE>
__global__ void __launch_bounds__(256)
k_fused(const float* __restrict__ A,
        const float* __restrict__ W1,
        const float* __restrict__ W2,
        const float* __restrict__ bias,
        const float* __restrict__ gamma,
        const float* __restrict__ beta,
        float* __restrict__ out) {
    __shared__ float s_a [16][68];    // A1^T tile [k][n]
    __shared__ float s_b [16][68];    // A2^T tile [k][n] (MODE 0 only)
    __shared__ float s_w1[16][132];   // W1^T tile [k][d]
    __shared__ float s_w2[16][132];   // W2^T tile [k][d] (MODE 0 only)

    const int tid = threadIdx.x;
    const int tx = tid & 15;          // 16 d-groups of 8
    const int ty = tid >> 4;          // 16 n-groups of 4
    const int n0 = blockIdx.x * 64;
    const int d0 = tx * 8;

    float acc[4][8];
#pragma unroll
    for (int i = 0; i < 4; i++)
#pragma unroll
        for (int j = 0; j < 8; j++) acc[i][j] = 0.0f;

    for (int k0 = 0; k0 < D; k0 += 16) {
        // load A1 (and A2) tiles, transposed to [k][n]
#pragma unroll
        for (int i = 0; i < 4; i++) {
            int idx = tid + i * 256;          // 0..1023
            int n  = idx >> 4;
            int kk = idx & 15;
            int gn = min(n0 + n, N_NODES - 1);
            float va;
            if (MODE == 0) va = dec_f(g_agg[gn * D + k0 + kk]);
            else           va = g_h[gn * D + k0 + kk];
            s_a[kk][n] = va;
            if (MODE == 0) s_b[kk][n] = __ldg(&A[gn * D + k0 + kk]);
        }
        // load W tiles, transposed to [k][d]
#pragma unroll
        for (int i = 0; i < 8; i++) {
            int idx = tid + i * 256;          // 0..2047
            int d  = idx >> 4;
            int kk = idx & 15;
            s_w1[kk][d] = __ldg(&W1[d * D + k0 + kk]);
            if (MODE == 0) s_w2[kk][d] = __ldg(&W2[d * D + k0 + kk]);
        }
        __syncthreads();

#pragma unroll
        for (int k = 0; k < 16; k++) {
            float4 a  = *reinterpret_cast<const float4*>(&s_a[k][ty * 4]);
            float4 w10 = *reinterpret_cast<const float4*>(&s_w1[k][d0]);
            float4 w11 = *reinterpret_cast<const float4*>(&s_w1[k][d0 + 4]);
            float av[4] = {a.x, a.y, a.z, a.w};
            float wv[8] = {w10.x, w10.y, w10.z, w10.w, w11.x, w11.y, w11.z, w11.w};
#pragma unroll
            for (int i = 0; i < 4; i++)
#pragma unroll
                for (int j = 0; j < 8; j++) acc[i][j] = fmaf(av[i], wv[j], acc[i][j]);
            if (MODE == 0) {
                float4 b  = *reinterpret_cast<const float4*>(&s_b[k][ty * 4]);
                float4 w20 = *reinterpret_cast<const float4*>(&s_w2[k][d0]);
                float4 w21 = *reinterpret_cast<const float4*>(&s_w2[k][d0 + 4]);
                float bv[4] = {b.x, b.y, b.z, b.w};
                float uv[8] = {w20.x, w20.y, w20.z, w20.w, w21.x, w21.y, w21.z, w21.w};
#pragma unroll
                for (int i = 0; i < 4; i++)
#pragma unroll
                    for (int j = 0; j < 8; j++) acc[i][j] = fmaf(bv[i], uv[j], acc[i][j]);
            }
        }
        __syncthreads();
    }

    // ---- epilogue: bias + gelu + skip + layernorm ----
    float4 bs0 = *reinterpret_cast<const float4*>(&bias[d0]);
    float4 bs1 = *reinterpret_cast<const float4*>(&bias[d0 + 4]);
    float bv[8] = {bs0.x, bs0.y, bs0.z, bs0.w, bs1.x, bs1.y, bs1.z, bs1.w};
    float4 gm0 = *reinterpret_cast<const float4*>(&gamma[d0]);
    float4 gm1 = *reinterpret_cast<const float4*>(&gamma[d0 + 4]);
    float gv8[8] = {gm0.x, gm0.y, gm0.z, gm0.w, gm1.x, gm1.y, gm1.z, gm1.w};
    float4 bt0 = *reinterpret_cast<const float4*>(&beta[d0]);
    float4 bt1 = *reinterpret_cast<const float4*>(&beta[d0 + 4]);
    float btv[8] = {bt0.x, bt0.y, bt0.z, bt0.w, bt1.x, bt1.y, bt1.z, bt1.w};

    float* dst = (MODE == 0) ? g_h : out;

#pragma unroll
    for (int i = 0; i < 4; i++) {
        int nl = ty * 4 + i;
        int gn = min(n0 + nl, N_NODES - 1);
        const float* skip_src = (MODE == 0) ? A : g_h;
        float4 sk0 = *reinterpret_cast<const float4*>(&skip_src[gn * D + d0]);
        float4 sk1 = *reinterpret_cast<const float4*>(&skip_src[gn * D + d0 + 4]);
        float sk[8] = {sk0.x, sk0.y, sk0.z, sk0.w, sk1.x, sk1.y, sk1.z, sk1.w};

        float g[8];
        float s1 = 0.0f, s2 = 0.0f;
#pragma unroll
        for (int j = 0; j < 8; j++) {
            float hp = acc[i][j] + bv[j];
            float val = gelu_exact(hp) + sk[j];
            g[j] = val;
            s1 += val;
            s2 += val * val;
        }
        // reduce across the 16 lanes (tx=0..15) sharing this node (within half-warp)
#pragma unroll
        for (int off = 8; off >= 1; off >>= 1) {
            s1 += __shfl_xor_sync(0xFFFFFFFFu, s1, off);
            s2 += __shfl_xor_sync(0xFFFFFFFFu, s2, off);
        }
        float mu = s1 * (1.0f / 128.0f);
        float var = fmaxf(s2 * (1.0f / 128.0f) - mu * mu, 0.0f);
        float rs = rsqrtf(var + 1e-5f);

        if (n0 + nl < N_NODES) {
            float o[8];
#pragma unroll
            for (int j = 0; j < 8; j++) o[j] = (g[j] - mu) * rs * gv8[j] + btv[j];
            float4 o0 = make_float4(o[0], o[1], o[2], o[3]);
            float4 o1 = make_float4(o[4], o[5], o[6], o[7]);
            *reinterpret_cast<float4*>(&dst[gn * D + d0])     = o0;
            *reinterpret_cast<float4*>(&dst[gn * D + d0 + 4]) = o1;
        }
    }
}

extern "C" void kernel_launch(void* const* d_in, const int* in_sizes, int n_in,
                              void* d_out, int out_size) {
    const float* x     = (const float*)d_in[0];
    const int*   ei    = (const int*)d_in[1];      // int32 (JAX default x64 off)
    const float* ew    = (const float*)d_in[2];
    const float* Wrel  = (const float*)d_in[3];
    const float* brel  = (const float*)d_in[4];
    const float* Wroot = (const float*)d_in[5];
    const float* linW  = (const float*)d_in[6];
    const float* linb  = (const float*)d_in[7];
    const float* gamma = (const float*)d_in[8];
    const float* beta  = (const float*)d_in[9];
    float* out = (float*)d_out;

    // 1) zero the aggregation buffer (sentinel 0 == empty)
    k_init<<<(N_NODES * D / 4 + 255) / 256, 256>>>();
    // 2) scatter-max messages
    k_scatter<<<(E_EDGES + 1) / 2, 256>>>(x, ei, ew);
    // 3) layer 1: agg@Wrel^T + b + x@Wroot^T -> gelu + x -> LN -> g_h
    k_fused<0><<<(N_NODES + 63) / 64, 256>>>(x, Wrel, Wroot, brel, gamma, beta, out);
    // 4) layer 2: g_h@linW^T + b -> gelu + g_h -> LN -> d_out
    k_fused<1><<<(N_NODES + 63) / 64, 256>>>(x, linW, Wroot, linb, gamma, beta, out);
    // 5) second output: pass-through edge_weight into the output tail (kernel copy;
    //    memcpy nodes are not capturable on this harness)
    if (out_size >= E_EDGES) {
        float* ew_dst = out + (out_size - E_EDGES);
        k_copy_ew<<<(E_EDGES / 4 + 255) / 256, 256>>>(ew, ew_dst);
    }
}

// round 4
// speedup vs baseline: 2.2524x; 2.2524x over previous
#include <cuda_runtime.h>
#include <math.h>

#define N_NODES 20000
#define D 128
#define E_EDGES 640000

// Scratch (static device globals; no allocation allowed)
__device__ float g_aggf[N_NODES * D];   // max-aggregated messages (0-filled if empty)
__device__ float g_h[N_NODES * D];      // layer-1 output
__device__ int   g_cnt[N_NODES];        // per-dst edge counts
__device__ int   g_off[N_NODES];        // exclusive prefix offsets
__device__ int   g_cur[N_NODES];        // bucket cursors
__device__ int2  g_edges[E_EDGES];      // sorted (src, weight_bits)

__device__ __forceinline__ float gelu_exact(float v) {
    return 0.5f * v * (1.0f + erff(v * 0.70710678118654752f));
}

// ---------------- zero the histogram ----------------
__global__ void k_zero_cnt() {
    int i = blockIdx.x * blockDim.x + threadIdx.x;
    if (i < N_NODES) g_cnt[i] = 0;
}

// ---------------- histogram of destination nodes ----------------
__global__ void k_hist(const int* __restrict__ ei) {
    int e = blockIdx.x * blockDim.x + threadIdx.x;
    if (e < E_EDGES) atomicAdd(&g_cnt[ei[E_EDGES + e]], 1);
}

// ---------------- single-block exclusive prefix scan over 20000 counts ----------------
__global__ void __launch_bounds__(1024) k_scan() {
    __shared__ int sp[1024];
    const int t = threadIdx.x;
    const int base = t * 20;
    int local[20];
    int s = 0;
#pragma unroll
    for (int i = 0; i < 20; i++) {
        int idx = base + i;
        int c = (idx < N_NODES) ? g_cnt[idx] : 0;
        local[i] = s;
        s += c;
    }
    sp[t] = s;
    __syncthreads();
    // inclusive Hillis-Steele scan over 1024 partials
    for (int off = 1; off < 1024; off <<= 1) {
        int add = (t >= off) ? sp[t - off] : 0;
        __syncthreads();
        sp[t] += add;
        __syncthreads();
    }
    int excl = (t > 0) ? sp[t - 1] : 0;
#pragma unroll
    for (int i = 0; i < 20; i++) {
        int idx = base + i;
        if (idx < N_NODES) {
            int o = excl + local[i];
            g_off[idx] = o;
            g_cur[idx] = o;
        }
    }
}

// ---------------- bucket edges by destination ----------------
__global__ void k_bucket(const int* __restrict__ ei, const float* __restrict__ ew) {
    int e = blockIdx.x * blockDim.x + threadIdx.x;
    if (e >= E_EDGES) return;
    int s = ei[e];
    int t = ei[E_EDGES + e];
    int p = atomicAdd(&g_cur[t], 1);
    g_edges[p] = make_int2(s, __float_as_int(__ldg(&ew[e])));
}

// ---------------- gather-max: one warp per node ----------------
__global__ void __launch_bounds__(256) k_gather(const float* __restrict__ x) {
    int nid = blockIdx.x * 8 + (threadIdx.x >> 5);
    int lane = threadIdx.x & 31;
    if (nid >= N_NODES) return;
    int start = g_off[nid];
    int cnt = g_cnt[nid];
    int end = start + cnt;
    float4 m = make_float4(-INFINITY, -INFINITY, -INFINITY, -INFINITY);
    int e = start;
    for (; e + 1 < end; e += 2) {
        int2 r0 = g_edges[e];
        int2 r1 = g_edges[e + 1];
        float w0 = __int_as_float(r0.y);
        float w1 = __int_as_float(r1.y);
        float4 x0 = *reinterpret_cast<const float4*>(&x[r0.x * D + lane * 4]);
        float4 x1 = *reinterpret_cast<const float4*>(&x[r1.x * D + lane * 4]);
        m.x = fmaxf(m.x, w0 * x0.x); m.y = fmaxf(m.y, w0 * x0.y);
        m.z = fmaxf(m.z, w0 * x0.z); m.w = fmaxf(m.w, w0 * x0.w);
        m.x = fmaxf(m.x, w1 * x1.x); m.y = fmaxf(m.y, w1 * x1.y);
        m.z = fmaxf(m.z, w1 * x1.z); m.w = fmaxf(m.w, w1 * x1.w);
    }
    if (e < end) {
        int2 r = g_edges[e];
        float w = __int_as_float(r.y);
        float4 xr = *reinterpret_cast<const float4*>(&x[r.x * D + lane * 4]);
        m.x = fmaxf(m.x, w * xr.x); m.y = fmaxf(m.y, w * xr.y);
        m.z = fmaxf(m.z, w * xr.z); m.w = fmaxf(m.w, w * xr.w);
    }
    if (cnt == 0) m = make_float4(0.f, 0.f, 0.f, 0.f);   // PyG empty-segment fill
    *reinterpret_cast<float4*>(&g_aggf[nid * D + lane * 4]) = m;
}

// ---------------- copy edge_weight to output tail ----------------
__global__ void k_copy_ew(const float* __restrict__ ew, float* __restrict__ dst) {
    int i = blockIdx.x * blockDim.x + threadIdx.x;
    if (i < E_EDGES / 4)
        reinterpret_cast<float4*>(dst)[i] = reinterpret_cast<const float4*>(ew)[i];
}

// ---------------- fused GEMM + bias + GELU + skip + LayerNorm ----------------
// MODE 0: acc = agg@W1^T + x@W2^T; skip = x;   dst = g_h
// MODE 1: acc = g_h@W1^T;          skip = g_h; dst = out
// 256 threads, tile 64 nodes x 128 cols, microtile 4n x 8d, kT=16, double-buffered.
template<int MODE>
__global__ void __launch_bounds__(256, 2)
k_fused(const float* __restrict__ A,          // x (mode0) / unused (mode1)
        const float* __restrict__ W1,
        const float* __restrict__ W2,
        const float* __restrict__ bias,
        const float* __restrict__ gamma,
        const float* __restrict__ beta,
        float* __restrict__ out) {
    __shared__ float s_a [2][16][68];
    __shared__ float s_w1[2][16][132];
    __shared__ float s_b [MODE == 0 ? 2 : 1][16][68];
    __shared__ float s_w2[MODE == 0 ? 2 : 1][16][132];

    const int tid = threadIdx.x;
    const int tx = tid & 15;          // 16 d-groups of 8
    const int ty = tid >> 4;          // 16 n-groups of 4
    const int n0 = blockIdx.x * 64;
    const int d0 = tx * 8;

    // load-role indices (float4 along k)
    const int n_ld = tid >> 2;        // 0..63
    const int kq   = tid & 3;         // 0..3
    const int gn_ld = min(n0 + n_ld, N_NODES - 1);
    const int wd0 = tid >> 2;         // 0..63
    const int wd1 = wd0 + 64;         // 64..127

    const float* Asrc = (MODE == 0) ? g_aggf : g_h;

    float4 ra, rb, rw1a, rw1b, rw2a, rw2b;

    auto load_regs = [&](int k0) {
        ra = *reinterpret_cast<const float4*>(&Asrc[gn_ld * D + k0 + kq * 4]);
        rw1a = *reinterpret_cast<const float4*>(&W1[wd0 * D + k0 + kq * 4]);
        rw1b = *reinterpret_cast<const float4*>(&W1[wd1 * D + k0 + kq * 4]);
        if (MODE == 0) {
            rb = *reinterpret_cast<const float4*>(&A[gn_ld * D + k0 + kq * 4]);
            rw2a = *reinterpret_cast<const float4*>(&W2[wd0 * D + k0 + kq * 4]);
            rw2b = *reinterpret_cast<const float4*>(&W2[wd1 * D + k0 + kq * 4]);
        }
    };
    auto store_smem = [&](int b) {
        s_a[b][kq * 4 + 0][n_ld] = ra.x;
        s_a[b][kq * 4 + 1][n_ld] = ra.y;
        s_a[b][kq * 4 + 2][n_ld] = ra.z;
        s_a[b][kq * 4 + 3][n_ld] = ra.w;
        s_w1[b][kq * 4 + 0][wd0] = rw1a.x;
        s_w1[b][kq * 4 + 1][wd0] = rw1a.y;
        s_w1[b][kq * 4 + 2][wd0] = rw1a.z;
        s_w1[b][kq * 4 + 3][wd0] = rw1a.w;
        s_w1[b][kq * 4 + 0][wd1] = rw1b.x;
        s_w1[b][kq * 4 + 1][wd1] = rw1b.y;
        s_w1[b][kq * 4 + 2][wd1] = rw1b.z;
        s_w1[b][kq * 4 + 3][wd1] = rw1b.w;
        if (MODE == 0) {
            s_b[b][kq * 4 + 0][n_ld] = rb.x;
            s_b[b][kq * 4 + 1][n_ld] = rb.y;
            s_b[b][kq * 4 + 2][n_ld] = rb.z;
            s_b[b][kq * 4 + 3][n_ld] = rb.w;
            s_w2[b][kq * 4 + 0][wd0] = rw2a.x;
            s_w2[b][kq * 4 + 1][wd0] = rw2a.y;
            s_w2[b][kq * 4 + 2][wd0] = rw2a.z;
            s_w2[b][kq * 4 + 3][wd0] = rw2a.w;
            s_w2[b][kq * 4 + 0][wd1] = rw2b.x;
            s_w2[b][kq * 4 + 1][wd1] = rw2b.y;
            s_w2[b][kq * 4 + 2][wd1] = rw2b.z;
            s_w2[b][kq * 4 + 3][wd1] = rw2b.w;
        }
    };

    float acc[4][8];
#pragma unroll
    for (int i = 0; i < 4; i++)
#pragma unroll
        for (int j = 0; j < 8; j++) acc[i][j] = 0.0f;

    load_regs(0);
    store_smem(0);
    __syncthreads();

#pragma unroll
    for (int it = 0; it < 8; it++) {
        const int b = it & 1;
        if (it < 7) load_regs((it + 1) * 16);

#pragma unroll
        for (int k = 0; k < 16; k++) {
            float4 a   = *reinterpret_cast<const float4*>(&s_a[b][k][ty * 4]);
            float4 w10 = *reinterpret_cast<const float4*>(&s_w1[b][k][d0]);
            float4 w11 = *reinterpret_cast<const float4*>(&s_w1[b][k][d0 + 4]);
            float av[4] = {a.x, a.y, a.z, a.w};
            float wv[8] = {w10.x, w10.y, w10.z, w10.w, w11.x, w11.y, w11.z, w11.w};
#pragma unroll
            for (int i = 0; i < 4; i++)
#pragma unroll
                for (int j = 0; j < 8; j++) acc[i][j] = fmaf(av[i], wv[j], acc[i][j]);
            if (MODE == 0) {
                float4 bb  = *reinterpret_cast<const float4*>(&s_b[b][k][ty * 4]);
                float4 w20 = *reinterpret_cast<const float4*>(&s_w2[b][k][d0]);
                float4 w21 = *reinterpret_cast<const float4*>(&s_w2[b][k][d0 + 4]);
                float bv2[4] = {bb.x, bb.y, bb.z, bb.w};
                float uv[8] = {w20.x, w20.y, w20.z, w20.w, w21.x, w21.y, w21.z, w21.w};
#pragma unroll
                for (int i = 0; i < 4; i++)
#pragma unroll
                    for (int j = 0; j < 8; j++) acc[i][j] = fmaf(bv2[i], uv[j], acc[i][j]);
            }
        }
        if (it < 7) {
            store_smem(b ^ 1);
            __syncthreads();
        }
    }

    // ---- epilogue: bias + gelu + skip + layernorm ----
    float4 bs0 = *reinterpret_cast<const float4*>(&bias[d0]);
    float4 bs1 = *reinterpret_cast<const float4*>(&bias[d0 + 4]);
    float bv[8] = {bs0.x, bs0.y, bs0.z, bs0.w, bs1.x, bs1.y, bs1.z, bs1.w};
    float4 gm0 = *reinterpret_cast<const float4*>(&gamma[d0]);
    float4 gm1 = *reinterpret_cast<const float4*>(&gamma[d0 + 4]);
    float gv8[8] = {gm0.x, gm0.y, gm0.z, gm0.w, gm1.x, gm1.y, gm1.z, gm1.w};
    float4 bt0 = *reinterpret_cast<const float4*>(&beta[d0]);
    float4 bt1 = *reinterpret_cast<const float4*>(&beta[d0 + 4]);
    float btv[8] = {bt0.x, bt0.y, bt0.z, bt0.w, bt1.x, bt1.y, bt1.z, bt1.w};

    float* dst = (MODE == 0) ? g_h : out;
    const float* skip_src = (MODE == 0) ? A : g_h;

#pragma unroll
    for (int i = 0; i < 4; i++) {
        int nl = ty * 4 + i;
        int gn = min(n0 + nl, N_NODES - 1);
        float4 sk0 = *reinterpret_cast<const float4*>(&skip_src[gn * D + d0]);
        float4 sk1 = *reinterpret_cast<const float4*>(&skip_src[gn * D + d0 + 4]);
        float sk[8] = {sk0.x, sk0.y, sk0.z, sk0.w, sk1.x, sk1.y, sk1.z, sk1.w};

        float g[8];
        float s1 = 0.0f, s2 = 0.0f;
#pragma unroll
        for (int j = 0; j < 8; j++) {
            float hp = acc[i][j] + bv[j];
            float val = gelu_exact(hp) + sk[j];
            g[j] = val;
            s1 += val;
            s2 += val * val;
        }
#pragma unroll
        for (int off = 8; off >= 1; off >>= 1) {
            s1 += __shfl_xor_sync(0xFFFFFFFFu, s1, off);
            s2 += __shfl_xor_sync(0xFFFFFFFFu, s2, off);
        }
        float mu = s1 * (1.0f / 128.0f);
        float var = fmaxf(s2 * (1.0f / 128.0f) - mu * mu, 0.0f);
        float rs = rsqrtf(var + 1e-5f);

        if (n0 + nl < N_NODES) {
            float o[8];
#pragma unroll
            for (int j = 0; j < 8; j++) o[j] = (g[j] - mu) * rs * gv8[j] + btv[j];
            *reinterpret_cast<float4*>(&dst[gn * D + d0])     = make_float4(o[0], o[1], o[2], o[3]);
            *reinterpret_cast<float4*>(&dst[gn * D + d0 + 4]) = make_float4(o[4], o[5], o[6], o[7]);
        }
    }
}

extern "C" void kernel_launch(void* const* d_in, const int* in_sizes, int n_in,
                              void* d_out, int out_size) {
    const float* x     = (const float*)d_in[0];
    const int*   ei    = (const int*)d_in[1];      // int32 (JAX x64 disabled)
    const float* ew    = (const float*)d_in[2];
    const float* Wrel  = (const float*)d_in[3];
    const float* brel  = (const float*)d_in[4];
    const float* Wroot = (const float*)d_in[5];
    const float* linW  = (const float*)d_in[6];
    const float* linb  = (const float*)d_in[7];
    const float* gamma = (const float*)d_in[8];
    const float* beta  = (const float*)d_in[9];
    float* out = (float*)d_out;

    // counting-sort the edges by destination, then gather-max (no fat atomics)
    k_zero_cnt<<<(N_NODES + 255) / 256, 256>>>();
    k_hist<<<(E_EDGES + 255) / 256, 256>>>(ei);
    k_scan<<<1, 1024>>>();
    k_bucket<<<(E_EDGES + 255) / 256, 256>>>(ei, ew);
    k_gather<<<(N_NODES + 7) / 8, 256>>>(x);
    // layer 1: agg@Wrel^T + b + x@Wroot^T -> gelu + x -> LN -> g_h
    k_fused<0><<<(N_NODES + 63) / 64, 256>>>(x, Wrel, Wroot, brel, gamma, beta, out);
    // layer 2: g_h@linW^T + b -> gelu + g_h -> LN -> out
    k_fused<1><<<(N_NODES + 63) / 64, 256>>>(x, linW, Wroot, linb, gamma, beta, out);
    // second output: pass-through edge_weight into the output tail
    if (out_size >= E_EDGES) {
        float* ew_dst = out + (out_size - E_EDGES);
        k_copy_ew<<<(E_EDGES / 4 + 255) / 256, 256>>>(ew, ew_dst);
    }
}

// round 5
// speedup vs baseline: 2.8496x; 1.2651x over previous
#include <cuda_runtime.h>
#include <math.h>

#define N_NODES 20000
#define D 128
#define E_EDGES 640000

// Scratch (static device globals; no allocation allowed)
__device__ float g_aggf[N_NODES * D];   // max-aggregated messages (0-filled if empty)
__device__ float g_h[N_NODES * D];      // layer-1 output
__device__ int   g_cnt[N_NODES];        // per-dst edge counts
__device__ int   g_off[N_NODES];        // exclusive prefix offsets
__device__ int   g_cur[N_NODES];        // bucket cursors
__device__ int2  g_edges[E_EDGES];      // sorted (src, weight_bits)
__device__ float g_WrelT[D * D];        // transposed weights [k][d]
__device__ float g_WrootT[D * D];
__device__ float g_linWT[D * D];

__device__ __forceinline__ float gelu_exact(float v) {
    return 0.5f * v * (1.0f + erff(v * 0.70710678118654752f));
}

// ---- cp.async helpers ----
__device__ __forceinline__ void cpa16(void* dst, const void* src) {
    unsigned d = (unsigned)__cvta_generic_to_shared(dst);
    asm volatile("cp.async.cg.shared.global [%0], [%1], 16;\n" :: "r"(d), "l"(src));
}
__device__ __forceinline__ void cpa_commit() { asm volatile("cp.async.commit_group;\n"); }
__device__ __forceinline__ void cpa_wait0()  { asm volatile("cp.async.wait_group 0;\n" ::: "memory"); }

// ---------------- prep: zero histogram + transpose the 3 weight matrices ----------------
__global__ void k_prep(const float* __restrict__ Wrel, const float* __restrict__ Wroot,
                       const float* __restrict__ linW) {
    int bid = blockIdx.x;
    int tid = threadIdx.x;
    if (bid < 79) {
        int i = bid * 256 + tid;
        if (i < N_NODES) g_cnt[i] = 0;
    } else {
        int i = (bid - 79) * 256 + tid;       // 0..49151
        int m = i >> 14;
        int r = i & 16383;                    // d*128 + k
        int d = r >> 7, k = r & 127;
        const float* src = (m == 0) ? Wrel : ((m == 1) ? Wroot : linW);
        float* dst = (m == 0) ? g_WrelT : ((m == 1) ? g_WrootT : g_linWT);
        dst[k * D + d] = src[r];
    }
}

// ---------------- histogram of destination nodes (4 edges/thread) ----------------
__global__ void k_hist(const int* __restrict__ ei) {
    int t = blockIdx.x * blockDim.x + threadIdx.x;          // 0..159999
    int4 d4 = reinterpret_cast<const int4*>(ei + E_EDGES)[t];
    atomicAdd(&g_cnt[d4.x], 1);
    atomicAdd(&g_cnt[d4.y], 1);
    atomicAdd(&g_cnt[d4.z], 1);
    atomicAdd(&g_cnt[d4.w], 1);
}

// ---------------- single-block exclusive prefix scan over 20000 counts ----------------
__global__ void __launch_bounds__(1024) k_scan() {
    __shared__ int sp[1024];
    const int t = threadIdx.x;
    const int base = t * 20;
    int local[20];
    int s = 0;
#pragma unroll
    for (int i = 0; i < 20; i++) {
        int idx = base + i;
        int c = (idx < N_NODES) ? g_cnt[idx] : 0;
        local[i] = s;
        s += c;
    }
    sp[t] = s;
    __syncthreads();
    for (int off = 1; off < 1024; off <<= 1) {
        int add = (t >= off) ? sp[t - off] : 0;
        __syncthreads();
        sp[t] += add;
        __syncthreads();
    }
    int excl = (t > 0) ? sp[t - 1] : 0;
#pragma unroll
    for (int i = 0; i < 20; i++) {
        int idx = base + i;
        if (idx < N_NODES) {
            int o = excl + local[i];
            g_off[idx] = o;
            g_cur[idx] = o;
        }
    }
}

// ---------------- bucket edges by destination (4 edges/thread) ----------------
__global__ void k_bucket(const int* __restrict__ ei, const float* __restrict__ ew) {
    int t = blockIdx.x * blockDim.x + threadIdx.x;
    int4  s4 = reinterpret_cast<const int4*>(ei)[t];
    int4  d4 = reinterpret_cast<const int4*>(ei + E_EDGES)[t];
    float4 w4 = reinterpret_cast<const float4*>(ew)[t];
    int p0 = atomicAdd(&g_cur[d4.x], 1);
    int p1 = atomicAdd(&g_cur[d4.y], 1);
    int p2 = atomicAdd(&g_cur[d4.z], 1);
    int p3 = atomicAdd(&g_cur[d4.w], 1);
    g_edges[p0] = make_int2(s4.x, __float_as_int(w4.x));
    g_edges[p1] = make_int2(s4.y, __float_as_int(w4.y));
    g_edges[p2] = make_int2(s4.z, __float_as_int(w4.z));
    g_edges[p3] = make_int2(s4.w, __float_as_int(w4.w));
}

// ---------------- gather-max: one warp per node, 4 edges per iteration ----------------
__global__ void __launch_bounds__(256) k_gather(const float* __restrict__ x) {
    int nid = blockIdx.x * 8 + (threadIdx.x >> 5);
    int lane = threadIdx.x & 31;
    if (nid >= N_NODES) return;
    int start = g_off[nid];
    int cnt = g_cnt[nid];
    int end = start + cnt;
    float4 m = make_float4(-INFINITY, -INFINITY, -INFINITY, -INFINITY);
    int e = start;
    for (; e + 3 < end; e += 4) {
        int2 r0 = g_edges[e + 0];
        int2 r1 = g_edges[e + 1];
        int2 r2 = g_edges[e + 2];
        int2 r3 = g_edges[e + 3];
        float4 x0 = *reinterpret_cast<const float4*>(&x[r0.x * D + lane * 4]);
        float4 x1 = *reinterpret_cast<const float4*>(&x[r1.x * D + lane * 4]);
        float4 x2 = *reinterpret_cast<const float4*>(&x[r2.x * D + lane * 4]);
        float4 x3 = *reinterpret_cast<const float4*>(&x[r3.x * D + lane * 4]);
        float w0 = __int_as_float(r0.y), w1 = __int_as_float(r1.y);
        float w2 = __int_as_float(r2.y), w3 = __int_as_float(r3.y);
        m.x = fmaxf(fmaxf(m.x, w0 * x0.x), fmaxf(w1 * x1.x, fmaxf(w2 * x2.x, w3 * x3.x)));
        m.y = fmaxf(fmaxf(m.y, w0 * x0.y), fmaxf(w1 * x1.y, fmaxf(w2 * x2.y, w3 * x3.y)));
        m.z = fmaxf(fmaxf(m.z, w0 * x0.z), fmaxf(w1 * x1.z, fmaxf(w2 * x2.z, w3 * x3.z)));
        m.w = fmaxf(fmaxf(m.w, w0 * x0.w), fmaxf(w1 * x1.w, fmaxf(w2 * x2.w, w3 * x3.w)));
    }
    for (; e < end; e++) {
        int2 r = g_edges[e];
        float w = __int_as_float(r.y);
        float4 xr = *reinterpret_cast<const float4*>(&x[r.x * D + lane * 4]);
        m.x = fmaxf(m.x, w * xr.x); m.y = fmaxf(m.y, w * xr.y);
        m.z = fmaxf(m.z, w * xr.z); m.w = fmaxf(m.w, w * xr.w);
    }
    if (cnt == 0) m = make_float4(0.f, 0.f, 0.f, 0.f);   // PyG empty-segment fill
    *reinterpret_cast<float4*>(&g_aggf[nid * D + lane * 4]) = m;
}

// ---------------- copy edge_weight to output tail ----------------
__global__ void k_copy_ew(const float* __restrict__ ew, float* __restrict__ dst) {
    int i = blockIdx.x * blockDim.x + threadIdx.x;
    if (i < E_EDGES / 4)
        reinterpret_cast<float4*>(dst)[i] = reinterpret_cast<const float4*>(ew)[i];
}

// ---------------- fused GEMM + bias + GELU + skip + LayerNorm ----------------
// MODE 0: acc = agg@Wrel^T + x@Wroot^T; skip = x;   dst = g_h
// MODE 1: acc = g_h@linW^T;             skip = g_h; dst = out
// 256 threads, tile 64 nodes x 128 cols, microtile 4n x (4+4)d, kT=16,
// 2-stage cp.async pipeline. A tiles in [n][k] (pad 20), W tiles in [k][d] (pad 132).
template<int MODE>
__global__ void __launch_bounds__(256, MODE == 0 ? 2 : 3)
k_fused(const float* __restrict__ X,     // x (mode0 operand-2 + skip); unused mode1
        const float* __restrict__ bias,
        const float* __restrict__ gamma,
        const float* __restrict__ beta,
        float* __restrict__ out) {
    __shared__ __align__(16) float s_a [2][64][20];
    __shared__ __align__(16) float s_w1[2][16][132];
    __shared__ __align__(16) float s_b [MODE == 0 ? 2 : 1][MODE == 0 ? 64 : 1][MODE == 0 ? 20 : 1];
    __shared__ __align__(16) float s_w2[MODE == 0 ? 2 : 1][MODE == 0 ? 16 : 1][MODE == 0 ? 132 : 1];

    const int tid = threadIdx.x;
    const int tx = tid & 15;
    const int ty = tid >> 4;
    const int n0 = blockIdx.x * 64;

    const float* Asrc = (MODE == 0) ? g_aggf : g_h;
    const float* W1T  = (MODE == 0) ? g_WrelT : g_linWT;
    const float* W2T  = g_WrootT;

    // load roles
    const int n_ld = tid >> 2;               // 0..63
    const int kq   = tid & 3;                // 16B chunk in k-tile
    const int gn_ld = min(n0 + n_ld, N_NODES - 1);

    auto issue = [&](int b, int k0) {
        cpa16(&s_a[b][n_ld][kq * 4], Asrc + gn_ld * D + k0 + kq * 4);
        if constexpr (MODE == 0)
            cpa16(&s_b[b][n_ld][kq * 4], X + gn_ld * D + k0 + kq * 4);
#pragma unroll
        for (int i = 0; i < 2; i++) {
            int idx = tid + i * 256;         // 0..511
            int kk = idx >> 5, dq = idx & 31;
            cpa16(&s_w1[b][kk][dq * 4], W1T + (k0 + kk) * D + dq * 4);
            if constexpr (MODE == 0)
                cpa16(&s_w2[b][kk][dq * 4], W2T + (k0 + kk) * D + dq * 4);
        }
        cpa_commit();
    };

    float acc[4][8];
#pragma unroll
    for (int i = 0; i < 4; i++)
#pragma unroll
        for (int j = 0; j < 8; j++) acc[i][j] = 0.0f;

    issue(0, 0);

#pragma unroll 1
    for (int it = 0; it < 8; it++) {
        const int b = it & 1;
        cpa_wait0();
        __syncthreads();
        if (it < 7) issue(b ^ 1, (it + 1) * 16);

#pragma unroll
        for (int k = 0; k < 16; k++) {
            float av[4];
#pragma unroll
            for (int i = 0; i < 4; i++) av[i] = s_a[b][ty * 4 + i][k];
            float4 wA = *reinterpret_cast<const float4*>(&s_w1[b][k][tx * 4]);
            float4 wB = *reinterpret_cast<const float4*>(&s_w1[b][k][64 + tx * 4]);
            float wv[8] = {wA.x, wA.y, wA.z, wA.w, wB.x, wB.y, wB.z, wB.w};
#pragma unroll
            for (int i = 0; i < 4; i++)
#pragma unroll
                for (int j = 0; j < 8; j++) acc[i][j] = fmaf(av[i], wv[j], acc[i][j]);
            if constexpr (MODE == 0) {
                float bv2[4];
#pragma unroll
                for (int i = 0; i < 4; i++) bv2[i] = s_b[b][ty * 4 + i][k];
                float4 uA = *reinterpret_cast<const float4*>(&s_w2[b][k][tx * 4]);
                float4 uB = *reinterpret_cast<const float4*>(&s_w2[b][k][64 + tx * 4]);
                float uv[8] = {uA.x, uA.y, uA.z, uA.w, uB.x, uB.y, uB.z, uB.w};
#pragma unroll
                for (int i = 0; i < 4; i++)
#pragma unroll
                    for (int j = 0; j < 8; j++) acc[i][j] = fmaf(bv2[i], uv[j], acc[i][j]);
            }
        }
    }

    // ---- epilogue: bias + gelu + skip + layernorm ----
    // thread covers d = [tx*4, tx*4+4) and [64+tx*4, 64+tx*4+4)
    const int dA = tx * 4, dB = 64 + tx * 4;
    float4 bsA = *reinterpret_cast<const float4*>(&bias[dA]);
    float4 bsB = *reinterpret_cast<const float4*>(&bias[dB]);
    float bv[8] = {bsA.x, bsA.y, bsA.z, bsA.w, bsB.x, bsB.y, bsB.z, bsB.w};
    float4 gmA = *reinterpret_cast<const float4*>(&gamma[dA]);
    float4 gmB = *reinterpret_cast<const float4*>(&gamma[dB]);
    float gv8[8] = {gmA.x, gmA.y, gmA.z, gmA.w, gmB.x, gmB.y, gmB.z, gmB.w};
    float4 btA = *reinterpret_cast<const float4*>(&beta[dA]);
    float4 btB = *reinterpret_cast<const float4*>(&beta[dB]);
    float btv[8] = {btA.x, btA.y, btA.z, btA.w, btB.x, btB.y, btB.z, btB.w};

    float* dst = (MODE == 0) ? g_h : out;
    const float* skip_src = (MODE == 0) ? X : g_h;

#pragma unroll
    for (int i = 0; i < 4; i++) {
        int nl = ty * 4 + i;
        int gn = min(n0 + nl, N_NODES - 1);
        float4 skA = *reinterpret_cast<const float4*>(&skip_src[gn * D + dA]);
        float4 skB = *reinterpret_cast<const float4*>(&skip_src[gn * D + dB]);
        float sk[8] = {skA.x, skA.y, skA.z, skA.w, skB.x, skB.y, skB.z, skB.w};

        float g[8];
        float s1 = 0.0f, s2 = 0.0f;
#pragma unroll
        for (int j = 0; j < 8; j++) {
            float hp = acc[i][j] + bv[j];
            float val = gelu_exact(hp) + sk[j];
            g[j] = val;
            s1 += val;
            s2 += val * val;
        }
#pragma unroll
        for (int off = 8; off >= 1; off >>= 1) {
            s1 += __shfl_xor_sync(0xFFFFFFFFu, s1, off);
            s2 += __shfl_xor_sync(0xFFFFFFFFu, s2, off);
        }
        float mu = s1 * (1.0f / 128.0f);
        float var = fmaxf(s2 * (1.0f / 128.0f) - mu * mu, 0.0f);
        float rs = rsqrtf(var + 1e-5f);

        if (n0 + nl < N_NODES) {
            float o[8];
#pragma unroll
            for (int j = 0; j < 8; j++) o[j] = (g[j] - mu) * rs * gv8[j] + btv[j];
            *reinterpret_cast<float4*>(&dst[gn * D + dA]) = make_float4(o[0], o[1], o[2], o[3]);
            *reinterpret_cast<float4*>(&dst[gn * D + dB]) = make_float4(o[4], o[5], o[6], o[7]);
        }
    }
}

extern "C" void kernel_launch(void* const* d_in, const int* in_sizes, int n_in,
                              void* d_out, int out_size) {
    const float* x     = (const float*)d_in[0];
    const int*   ei    = (const int*)d_in[1];      // int32 (JAX x64 disabled)
    const float* ew    = (const float*)d_in[2];
    const float* Wrel  = (const float*)d_in[3];
    const float* brel  = (const float*)d_in[4];
    const float* Wroot = (const float*)d_in[5];
    const float* linW  = (const float*)d_in[6];
    const float* linb  = (const float*)d_in[7];
    const float* gamma = (const float*)d_in[8];
    const float* beta  = (const float*)d_in[9];
    float* out = (float*)d_out;

    // prep: zero histogram + transpose weights
    k_prep<<<79 + 192, 256>>>(Wrel, Wroot, linW);
    // counting-sort the edges by destination, then gather-max
    k_hist<<<E_EDGES / 4 / 256, 256>>>(ei);
    k_scan<<<1, 1024>>>();
    k_bucket<<<E_EDGES / 4 / 256, 256>>>(ei, ew);
    k_gather<<<(N_NODES + 7) / 8, 256>>>(x);
    // layer 1: agg@Wrel^T + b + x@Wroot^T -> gelu + x -> LN -> g_h
    k_fused<0><<<(N_NODES + 63) / 64, 256>>>(x, brel, gamma, beta, out);
    // layer 2: g_h@linW^T + b -> gelu + g_h -> LN -> out
    k_fused<1><<<(N_NODES + 63) / 64, 256>>>(x, linb, gamma, beta, out);
    // second output: pass-through edge_weight into the output tail
    if (out_size >= E_EDGES) {
        float* ew_dst = out + (out_size - E_EDGES);
        k_copy_ew<<<(E_EDGES / 4 + 255) / 256, 256>>>(ew, ew_dst);
    }
}